// round 6
// baseline (speedup 1.0000x reference)
#include <cuda_runtime.h>
#include <cuda_bf16.h>
#include <cuda_fp16.h>
#include <cstdint>

#define N_NODES 100000
#define N_EDGES 1600000
#define FEAT    128

#define SCAN_BLK   512
#define SCAN_NBLK  ((N_NODES + SCAN_BLK - 1) / SCAN_BLK)   // 196

// ---------------- device scratch (no allocations allowed) ----------------
__device__ float g_bufA[N_NODES * FEAT];
__device__ float g_bufB[N_NODES * FEAT];
__device__ __half g_h16[N_NODES * FEAT];          // fp16 gather copy of current features
__device__ int   g_rowstart[N_NODES + 1];
__device__ int   g_cursor[N_NODES];
__device__ float g_invdeg[N_NODES];
__device__ int   g_csr_src[N_EDGES];
__device__ int   g_blksum[SCAN_NBLK];
__device__ int   g_blkoff[SCAN_NBLK];
__device__ __nv_bfloat16 g_whi[3 * FEAT * FEAT];   // [n][k] (K contiguous) = col-major B
__device__ __nv_bfloat16 g_wlo[3 * FEAT * FEAT];

// ---------------- helpers ----------------
__device__ __forceinline__ uint32_t smem_u32(const void* p) {
    uint32_t a;
    asm("{ .reg .u64 t; cvta.to.shared.u64 t, %1; cvt.u32.u64 %0, t; }" : "=r"(a) : "l"(p));
    return a;
}

__device__ __forceinline__ void ldmatrix_x4(uint32_t* r, uint32_t addr) {
    asm volatile("ldmatrix.sync.aligned.m8n8.x4.shared.b16 {%0,%1,%2,%3}, [%4];"
                 : "=r"(r[0]), "=r"(r[1]), "=r"(r[2]), "=r"(r[3]) : "r"(addr));
}
__device__ __forceinline__ void ldmatrix_x2(uint32_t* r, uint32_t addr) {
    asm volatile("ldmatrix.sync.aligned.m8n8.x2.shared.b16 {%0,%1}, [%2];"
                 : "=r"(r[0]), "=r"(r[1]) : "r"(addr));
}
__device__ __forceinline__ void mma16816(float* c, const uint32_t* a, const uint32_t* b) {
    asm volatile("mma.sync.aligned.m16n8k16.row.col.f32.bf16.bf16.f32 "
                 "{%0,%1,%2,%3}, {%4,%5,%6,%7}, {%8,%9}, {%0,%1,%2,%3};"
                 : "+f"(c[0]), "+f"(c[1]), "+f"(c[2]), "+f"(c[3])
                 : "r"(a[0]), "r"(a[1]), "r"(a[2]), "r"(a[3]), "r"(b[0]), "r"(b[1]));
}

__device__ __forceinline__ float4 h4_to_f4(uint2 u) {
    __half2 a = *reinterpret_cast<__half2*>(&u.x);
    __half2 b = *reinterpret_cast<__half2*>(&u.y);
    float2 fa = __half22float2(a);
    float2 fb = __half22float2(b);
    return make_float4(fa.x, fa.y, fb.x, fb.y);
}

// ---------------- CSR build ----------------
__global__ void zero_cursor_kernel() {
    int i = blockIdx.x * blockDim.x + threadIdx.x;
    if (i < N_NODES) g_cursor[i] = 0;
}

__global__ void hist_kernel(const int* __restrict__ dst) {
    int e = blockIdx.x * blockDim.x + threadIdx.x;
    if (e < N_EDGES) atomicAdd(&g_cursor[dst[e]], 1);
}

// pass 1: per-block sums of the degree histogram (coalesced, all SMs)
__global__ void scan_reduce_kernel() {
    int b = blockIdx.x;
    int i0 = b * SCAN_BLK + threadIdx.x;
    int i1 = i0 + 256;
    int v = 0;
    if (i0 < N_NODES) v += g_cursor[i0];
    if (i1 < N_NODES && (threadIdx.x + 256) < SCAN_BLK) v += g_cursor[i1];
    #pragma unroll
    for (int off = 16; off > 0; off >>= 1) v += __shfl_down_sync(0xFFFFFFFFu, v, off);
    __shared__ int ws[8];
    int lane = threadIdx.x & 31, w = threadIdx.x >> 5;
    if (lane == 0) ws[w] = v;
    __syncthreads();
    if (w == 0) {
        int s = (lane < 8) ? ws[lane] : 0;
        #pragma unroll
        for (int off = 4; off > 0; off >>= 1) s += __shfl_down_sync(0xFFFFFFFFu, s, off);
        if (lane == 0) g_blksum[b] = s;
    }
}

// pass 2: single block scans the block sums (exclusive) and writes total
__global__ void scan_blocksums_kernel() {
    int t = threadIdx.x;  // 256 threads
    int v = (t < SCAN_NBLK) ? g_blksum[t] : 0;
    int orig = v;
    int lane = t & 31, w = t >> 5;
    #pragma unroll
    for (int off = 1; off < 32; off <<= 1) {
        int n = __shfl_up_sync(0xFFFFFFFFu, v, off);
        if (lane >= off) v += n;
    }
    __shared__ int ws[8];
    if (lane == 31) ws[w] = v;
    __syncthreads();
    if (t < 8) {
        int s = ws[t];
        #pragma unroll
        for (int off = 1; off < 8; off <<= 1) {
            int n = __shfl_up_sync(0xFFu, s, off);
            if ((t & 7) >= off) s += n;
        }
        ws[t] = s;
    }
    __syncthreads();
    int base = (w > 0) ? ws[w - 1] : 0;
    int incl = base + v;
    if (t < SCAN_NBLK) g_blkoff[t] = incl - orig;  // exclusive
    if (t == SCAN_NBLK - 1) g_rowstart[N_NODES] = incl;
}

// pass 3: block-local exclusive scan + write rowstart/cursor/invdeg (coalesced)
__global__ void scan_write_kernel() {
    int i = blockIdx.x * SCAN_BLK + threadIdx.x;   // 512 threads, 1 elem each
    int d = (i < N_NODES) ? g_cursor[i] : 0;
    int lane = threadIdx.x & 31, w = threadIdx.x >> 5;
    int v = d;
    #pragma unroll
    for (int off = 1; off < 32; off <<= 1) {
        int n = __shfl_up_sync(0xFFFFFFFFu, v, off);
        if (lane >= off) v += n;
    }
    __shared__ int ws[16];
    if (lane == 31) ws[w] = v;
    __syncthreads();
    if (threadIdx.x < 16) {
        int s = ws[threadIdx.x];
        #pragma unroll
        for (int off = 1; off < 16; off <<= 1) {
            int n = __shfl_up_sync(0xFFFFu, s, off);
            if (threadIdx.x >= off) s += n;
        }
        ws[threadIdx.x] = s;
    }
    __syncthreads();
    int base = (w > 0) ? ws[w - 1] : 0;
    int excl = g_blkoff[blockIdx.x] + base + v - d;
    if (i < N_NODES) {
        g_rowstart[i] = excl;
        g_cursor[i]   = excl;
        g_invdeg[i]   = 1.0f / fmaxf((float)d, 1.0f);
    }
}

__global__ void scatter_kernel(const int* __restrict__ src, const int* __restrict__ dst) {
    int e = blockIdx.x * blockDim.x + threadIdx.x;
    if (e < N_EDGES) {
        int pos = atomicAdd(&g_cursor[dst[e]], 1);
        g_csr_src[pos] = src[e];
    }
}

// ---------------- weight prep: fp32 W[k][n] -> bf16 hi/lo in [n][k] ----------------
__global__ void convw_kernel(const float* __restrict__ W1, const float* __restrict__ W2,
                             const float* __restrict__ W3) {
    int i = blockIdx.x * blockDim.x + threadIdx.x;
    if (i >= 3 * FEAT * FEAT) return;
    int l = i >> 14, r = i & 16383;
    int n = r >> 7, k = r & 127;
    const float* W = (l == 0) ? W1 : ((l == 1) ? W2 : W3);
    float v = W[k * FEAT + n];
    __nv_bfloat16 h = __float2bfloat16(v);
    g_whi[i] = h;
    g_wlo[i] = __float2bfloat16(v - __bfloat162float(h));
}

// ---------------- x -> fp16 copy (layer-1 gather table) ----------------
__global__ void convx_kernel(const float2* __restrict__ x2) {
    int i = blockIdx.x * blockDim.x + threadIdx.x;
    if (i < N_NODES * 64) {
        float2 v = __ldg(&x2[i]);
        reinterpret_cast<__half2*>(g_h16)[i] = __floats2half2_rn(v.x, v.y);
    }
}

// ---------------- aggregation: out = h + inv_deg * sum_{src} h16[src] ----------------
// Gather reads the fp16 table (256B/row, half the L2 traffic); self term + accum fp32.
__global__ void agg_kernel(const float4* __restrict__ hself, float4* __restrict__ out4) {
    int warp = (blockIdx.x * blockDim.x + threadIdx.x) >> 5;
    if (warp >= N_NODES) return;
    int lane = threadIdx.x & 31;

    const uint2* h16 = reinterpret_cast<const uint2*>(g_h16);  // 32 uint2 per row

    int s = g_rowstart[warp];
    int e = g_rowstart[warp + 1];

    float4 acc = make_float4(0.f, 0.f, 0.f, 0.f);
    int i = s;
    for (; i + 4 <= e; i += 4) {
        int s0 = g_csr_src[i + 0];
        int s1 = g_csr_src[i + 1];
        int s2 = g_csr_src[i + 2];
        int s3 = g_csr_src[i + 3];
        float4 v0 = h4_to_f4(__ldg(&h16[s0 * 32 + lane]));
        float4 v1 = h4_to_f4(__ldg(&h16[s1 * 32 + lane]));
        float4 v2 = h4_to_f4(__ldg(&h16[s2 * 32 + lane]));
        float4 v3 = h4_to_f4(__ldg(&h16[s3 * 32 + lane]));
        acc.x += (v0.x + v1.x) + (v2.x + v3.x);
        acc.y += (v0.y + v1.y) + (v2.y + v3.y);
        acc.z += (v0.z + v1.z) + (v2.z + v3.z);
        acc.w += (v0.w + v1.w) + (v2.w + v3.w);
    }
    for (; i < e; i++) {
        int s0 = g_csr_src[i];
        float4 v = h4_to_f4(__ldg(&h16[s0 * 32 + lane]));
        acc.x += v.x; acc.y += v.y; acc.z += v.z; acc.w += v.w;
    }

    float w = g_invdeg[warp];
    float4 self = __ldg(&hself[warp * 32 + lane]);
    float4 o;
    o.x = self.x + acc.x * w;
    o.y = self.y + acc.y * w;
    o.z = self.z + acc.z * w;
    o.w = self.w + acc.w * w;
    out4[warp * 32 + lane] = o;
}

// ---------------- HMMA GEMM: out[M,128] = [relu](A[M,128] @ W + b) ----------------
// bf16 hi/lo split via mma.sync: D = aHi*wHi + aHi*wLo + aLo*wHi.
// Epilogue optionally dual-writes an fp16 copy (gather table for the next layer).
#define APITCH 136
#define GEMM_SMEM_BYTES (4 * 128 * APITCH * 2)

__global__ void __launch_bounds__(256, 1)
mma_gemm_kernel(const float* __restrict__ A,
                const __nv_bfloat16* __restrict__ whi,
                const __nv_bfloat16* __restrict__ wlo,
                const float* __restrict__ bias,
                float* __restrict__ out, __half2* __restrict__ out16,
                int M, int do_relu) {
    extern __shared__ __nv_bfloat16 sm[];
    __nv_bfloat16* sAhi = sm;
    __nv_bfloat16* sAlo = sm + 128 * APITCH;
    __nv_bfloat16* sWhi = sm + 2 * 128 * APITCH;
    __nv_bfloat16* sWlo = sm + 3 * 128 * APITCH;

    const int tid  = threadIdx.x;
    const int lane = tid & 31;
    const int wid  = tid >> 5;
    const int row0 = blockIdx.x * 128;
    const int rows = min(128, M - row0);

    if (rows < 128) {
        uint32_t z = 0;
        uint32_t base = smem_u32(sAhi);
        for (int idx = tid; idx < 2 * 128 * APITCH / 2; idx += 256)
            asm volatile("st.shared.b32 [%0], %1;" :: "r"(base + idx * 4), "r"(z) : "memory");
        __syncthreads();
    }

    {
        const float4* A4 = reinterpret_cast<const float4*>(A);
        for (int idx = tid; idx < rows * 32; idx += 256) {
            int r = idx >> 5, c4 = idx & 31;
            float4 a = __ldg(&A4[(size_t)(row0 + r) * 32 + c4]);
            __nv_bfloat162 h0 = __floats2bfloat162_rn(a.x, a.y);
            __nv_bfloat162 h1 = __floats2bfloat162_rn(a.z, a.w);
            float2 f0 = __bfloat1622float2(h0);
            float2 f1 = __bfloat1622float2(h1);
            __nv_bfloat162 l0 = __floats2bfloat162_rn(a.x - f0.x, a.y - f0.y);
            __nv_bfloat162 l1 = __floats2bfloat162_rn(a.z - f1.x, a.w - f1.y);
            int eoff = r * APITCH + c4 * 4;
            *reinterpret_cast<__nv_bfloat162*>(sAhi + eoff)     = h0;
            *reinterpret_cast<__nv_bfloat162*>(sAhi + eoff + 2) = h1;
            *reinterpret_cast<__nv_bfloat162*>(sAlo + eoff)     = l0;
            *reinterpret_cast<__nv_bfloat162*>(sAlo + eoff + 2) = l1;
        }
    }

    {
        const uint4* wh4 = reinterpret_cast<const uint4*>(whi);
        const uint4* wl4 = reinterpret_cast<const uint4*>(wlo);
        for (int idx = tid; idx < 2048; idx += 256) {
            int r = idx >> 4, c16 = idx & 15;
            int eoff = r * APITCH + c16 * 8;
            *reinterpret_cast<uint4*>(sWhi + eoff) = __ldg(&wh4[idx]);
            *reinterpret_cast<uint4*>(sWlo + eoff) = __ldg(&wl4[idx]);
        }
    }
    __syncthreads();

    const int wm = wid & 3;
    const int wn = wid >> 2;

    float acc[2][8][4];
    #pragma unroll
    for (int i = 0; i < 2; i++)
        #pragma unroll
        for (int j = 0; j < 8; j++)
            #pragma unroll
            for (int c = 0; c < 4; c++) acc[i][j][c] = 0.f;

    const uint32_t aRowOff = (uint32_t)(((wm * 32 + (lane & 15)) * APITCH + (lane >> 4) * 8) * 2);
    const uint32_t bRowOff = (uint32_t)(((wn * 64 + (lane & 7)) * APITCH + ((lane >> 3) & 1) * 8) * 2);

    #pragma unroll
    for (int pass = 0; pass < 3; pass++) {
        const __nv_bfloat16* pA = (pass == 2) ? sAlo : sAhi;
        const __nv_bfloat16* pW = (pass == 1) ? sWlo : sWhi;
        uint32_t aAddr = smem_u32(pA) + aRowOff;
        uint32_t bAddr = smem_u32(pW) + bRowOff;

        #pragma unroll
        for (int kk = 0; kk < 8; kk++) {
            uint32_t a0[4], a1[4];
            ldmatrix_x4(a0, aAddr + kk * 32);
            ldmatrix_x4(a1, aAddr + 16 * APITCH * 2 + kk * 32);
            #pragma unroll
            for (int tn = 0; tn < 8; tn++) {
                uint32_t b[2];
                ldmatrix_x2(b, bAddr + tn * 8 * APITCH * 2 + kk * 32);
                mma16816(acc[0][tn], a0, b);
                mma16816(acc[1][tn], a1, b);
            }
        }
    }

    #pragma unroll
    for (int tm = 0; tm < 2; tm++) {
        int rbase = wm * 32 + tm * 16 + (lane >> 2);
        #pragma unroll
        for (int half = 0; half < 2; half++) {
            int r = rbase + half * 8;
            if (r < rows) {
                float* orow = out + (size_t)(row0 + r) * 128;
                __half2* hrow = out16 ? (out16 + (size_t)(row0 + r) * 64) : nullptr;
                #pragma unroll
                for (int tn = 0; tn < 8; tn++) {
                    int c = wn * 64 + tn * 8 + (lane & 3) * 2;
                    float2 o;
                    o.x = acc[tm][tn][half * 2 + 0] + __ldg(&bias[c + 0]);
                    o.y = acc[tm][tn][half * 2 + 1] + __ldg(&bias[c + 1]);
                    if (do_relu) { o.x = fmaxf(o.x, 0.f); o.y = fmaxf(o.y, 0.f); }
                    *reinterpret_cast<float2*>(orow + c) = o;
                    if (hrow) hrow[c >> 1] = __floats2half2_rn(o.x, o.y);
                }
            }
        }
    }
}

// ---------------- launch ----------------
extern "C" void kernel_launch(void* const* d_in, const int* in_sizes, int n_in,
                              void* d_out, int out_size) {
    const float* x        = (const float*)d_in[0];
    const float* W1       = (const float*)d_in[1];
    const float* b1       = (const float*)d_in[2];
    const float* W2       = (const float*)d_in[3];
    const float* b2       = (const float*)d_in[4];
    const float* W3       = (const float*)d_in[5];
    const float* b3       = (const float*)d_in[6];
    const int*   edge_src = (const int*)d_in[7];
    const int*   edge_dst = (const int*)d_in[8];
    float* out = (float*)d_out;

    (void)in_sizes; (void)n_in; (void)out_size;

    cudaFuncSetAttribute(mma_gemm_kernel,
                         cudaFuncAttributeMaxDynamicSharedMemorySize, GEMM_SMEM_BYTES);

    float* bufA; float* bufB;
    __nv_bfloat16* whi; __nv_bfloat16* wlo;
    __half* h16;
    cudaGetSymbolAddress((void**)&bufA, g_bufA);
    cudaGetSymbolAddress((void**)&bufB, g_bufB);
    cudaGetSymbolAddress((void**)&whi, g_whi);
    cudaGetSymbolAddress((void**)&wlo, g_wlo);
    cudaGetSymbolAddress((void**)&h16, g_h16);
    __half2* h16_2 = (__half2*)h16;

    const int M = N_NODES;
    const int edgeBlocks = (N_EDGES + 255) / 256;
    const int nodeBlocks = (N_NODES + 255) / 256;
    const int aggBlocks  = (N_NODES * 32 + 255) / 256;
    const int gemmBlocks = (M + 127) / 128;

    // weight + x16 prep (independent; overlaps CSR build)
    convw_kernel<<<(3 * FEAT * FEAT + 255) / 256, 256>>>(W1, W2, W3);
    convx_kernel<<<(N_NODES * 64 + 255) / 256, 256>>>((const float2*)x);

    // CSR build (parallel 3-pass scan)
    zero_cursor_kernel<<<nodeBlocks, 256>>>();
    hist_kernel<<<edgeBlocks, 256>>>(edge_dst);
    scan_reduce_kernel<<<SCAN_NBLK, 256>>>();
    scan_blocksums_kernel<<<1, 256>>>();
    scan_write_kernel<<<SCAN_NBLK, SCAN_BLK>>>();
    scatter_kernel<<<edgeBlocks, 256>>>(edge_src, edge_dst);

    // layer 1: agg(x via h16) -> gemm (writes bufB fp32 + h16 fp16)
    agg_kernel<<<aggBlocks, 256>>>((const float4*)x, (float4*)bufA);
    mma_gemm_kernel<<<gemmBlocks, 256, GEMM_SMEM_BYTES>>>(bufA, whi, wlo, b1, bufB, h16_2, M, 1);
    // layer 2
    agg_kernel<<<aggBlocks, 256>>>((const float4*)bufB, (float4*)bufA);
    mma_gemm_kernel<<<gemmBlocks, 256, GEMM_SMEM_BYTES>>>(bufA, whi + FEAT * FEAT, wlo + FEAT * FEAT, b2, bufB, h16_2, M, 1);
    // layer 3 (no fp16 copy needed)
    agg_kernel<<<aggBlocks, 256>>>((const float4*)bufB, (float4*)bufA);
    mma_gemm_kernel<<<gemmBlocks, 256, GEMM_SMEM_BYTES>>>(bufA, whi + 2 * FEAT * FEAT, wlo + 2 * FEAT * FEAT, b3, out, (half2*)nullptr, M, 0);
}

// round 7
// speedup vs baseline: 1.0540x; 1.0540x over previous
#include <cuda_runtime.h>
#include <cuda_bf16.h>
#include <cstdint>

#define N_NODES 100000
#define N_EDGES 1600000
#define FEAT    128

#define SCAN_BLK   512
#define SCAN_NBLK  ((N_NODES + SCAN_BLK - 1) / SCAN_BLK)   // 196

// ---------------- device scratch (no allocations allowed) ----------------
__device__ float g_bufA[N_NODES * FEAT];
__device__ float g_bufB[N_NODES * FEAT];
__device__ int   g_rowstart[N_NODES + 1];
__device__ int   g_cursor[N_NODES];
__device__ float g_invdeg[N_NODES];
__device__ int   g_csr_src[N_EDGES];
__device__ int   g_blksum[SCAN_NBLK];
__device__ int   g_blkoff[SCAN_NBLK];
__device__ __nv_bfloat16 g_whi[3 * FEAT * FEAT];   // [n][k] (K contiguous) = col-major B
__device__ __nv_bfloat16 g_wlo[3 * FEAT * FEAT];

// ---------------- helpers ----------------
__device__ __forceinline__ uint32_t smem_u32(const void* p) {
    uint32_t a;
    asm("{ .reg .u64 t; cvta.to.shared.u64 t, %1; cvt.u32.u64 %0, t; }" : "=r"(a) : "l"(p));
    return a;
}

__device__ __forceinline__ void ldmatrix_x4(uint32_t* r, uint32_t addr) {
    asm volatile("ldmatrix.sync.aligned.m8n8.x4.shared.b16 {%0,%1,%2,%3}, [%4];"
                 : "=r"(r[0]), "=r"(r[1]), "=r"(r[2]), "=r"(r[3]) : "r"(addr));
}
__device__ __forceinline__ void ldmatrix_x2(uint32_t* r, uint32_t addr) {
    asm volatile("ldmatrix.sync.aligned.m8n8.x2.shared.b16 {%0,%1}, [%2];"
                 : "=r"(r[0]), "=r"(r[1]) : "r"(addr));
}
__device__ __forceinline__ void mma16816(float* c, const uint32_t* a, const uint32_t* b) {
    asm volatile("mma.sync.aligned.m16n8k16.row.col.f32.bf16.bf16.f32 "
                 "{%0,%1,%2,%3}, {%4,%5,%6,%7}, {%8,%9}, {%0,%1,%2,%3};"
                 : "+f"(c[0]), "+f"(c[1]), "+f"(c[2]), "+f"(c[3])
                 : "r"(a[0]), "r"(a[1]), "r"(a[2]), "r"(a[3]), "r"(b[0]), "r"(b[1]));
}

// ---------------- CSR build ----------------
__global__ void zero_cursor_kernel() {
    int i = blockIdx.x * blockDim.x + threadIdx.x;
    if (i < N_NODES) g_cursor[i] = 0;
}

__global__ void hist_kernel(const int* __restrict__ dst) {
    int e = blockIdx.x * blockDim.x + threadIdx.x;
    if (e < N_EDGES) atomicAdd(&g_cursor[dst[e]], 1);
}

// pass 1: per-block sums of the degree histogram (coalesced, all SMs)
__global__ void scan_reduce_kernel() {
    int b = blockIdx.x;
    int i0 = b * SCAN_BLK + threadIdx.x;
    int i1 = i0 + 256;
    int v = 0;
    if (i0 < N_NODES) v += g_cursor[i0];
    if (i1 < N_NODES && (threadIdx.x + 256) < SCAN_BLK) v += g_cursor[i1];
    #pragma unroll
    for (int off = 16; off > 0; off >>= 1) v += __shfl_down_sync(0xFFFFFFFFu, v, off);
    __shared__ int ws[8];
    int lane = threadIdx.x & 31, w = threadIdx.x >> 5;
    if (lane == 0) ws[w] = v;
    __syncthreads();
    if (w == 0) {
        int s = (lane < 8) ? ws[lane] : 0;
        #pragma unroll
        for (int off = 4; off > 0; off >>= 1) s += __shfl_down_sync(0xFFFFFFFFu, s, off);
        if (lane == 0) g_blksum[b] = s;
    }
}

// pass 2: single block scans the block sums (exclusive) and writes total
__global__ void scan_blocksums_kernel() {
    int t = threadIdx.x;  // 256 threads
    int v = (t < SCAN_NBLK) ? g_blksum[t] : 0;
    int orig = v;
    int lane = t & 31, w = t >> 5;
    #pragma unroll
    for (int off = 1; off < 32; off <<= 1) {
        int n = __shfl_up_sync(0xFFFFFFFFu, v, off);
        if (lane >= off) v += n;
    }
    __shared__ int ws[8];
    if (lane == 31) ws[w] = v;
    __syncthreads();
    if (t < 8) {
        int s = ws[t];
        #pragma unroll
        for (int off = 1; off < 8; off <<= 1) {
            int n = __shfl_up_sync(0xFFu, s, off);
            if ((t & 7) >= off) s += n;
        }
        ws[t] = s;
    }
    __syncthreads();
    int base = (w > 0) ? ws[w - 1] : 0;
    int incl = base + v;
    if (t < SCAN_NBLK) g_blkoff[t] = incl - orig;  // exclusive
    if (t == SCAN_NBLK - 1) g_rowstart[N_NODES] = incl;
}

// pass 3: block-local exclusive scan + write rowstart/cursor/invdeg (coalesced)
__global__ void scan_write_kernel() {
    int i = blockIdx.x * SCAN_BLK + threadIdx.x;   // 512 threads, 1 elem each
    int d = (i < N_NODES) ? g_cursor[i] : 0;
    int lane = threadIdx.x & 31, w = threadIdx.x >> 5;
    int v = d;
    #pragma unroll
    for (int off = 1; off < 32; off <<= 1) {
        int n = __shfl_up_sync(0xFFFFFFFFu, v, off);
        if (lane >= off) v += n;
    }
    __shared__ int ws[16];
    if (lane == 31) ws[w] = v;
    __syncthreads();
    if (threadIdx.x < 16) {
        int s = ws[threadIdx.x];
        #pragma unroll
        for (int off = 1; off < 16; off <<= 1) {
            int n = __shfl_up_sync(0xFFFFu, s, off);
            if (threadIdx.x >= off) s += n;
        }
        ws[threadIdx.x] = s;
    }
    __syncthreads();
    int base = (w > 0) ? ws[w - 1] : 0;
    int excl = g_blkoff[blockIdx.x] + base + v - d;
    if (i < N_NODES) {
        g_rowstart[i] = excl;
        g_cursor[i]   = excl;
        g_invdeg[i]   = 1.0f / fmaxf((float)d, 1.0f);
    }
}

__global__ void scatter_kernel(const int* __restrict__ src, const int* __restrict__ dst) {
    int e = blockIdx.x * blockDim.x + threadIdx.x;
    if (e < N_EDGES) {
        int pos = atomicAdd(&g_cursor[dst[e]], 1);
        g_csr_src[pos] = src[e];
    }
}

// ---------------- weight prep: fp32 W[k][n] -> bf16 hi/lo in [n][k] ----------------
__global__ void convw_kernel(const float* __restrict__ W1, const float* __restrict__ W2,
                             const float* __restrict__ W3) {
    int i = blockIdx.x * blockDim.x + threadIdx.x;
    if (i >= 3 * FEAT * FEAT) return;
    int l = i >> 14, r = i & 16383;
    int n = r >> 7, k = r & 127;
    const float* W = (l == 0) ? W1 : ((l == 1) ? W2 : W3);
    float v = W[k * FEAT + n];
    __nv_bfloat16 h = __float2bfloat16(v);
    g_whi[i] = h;
    g_wlo[i] = __float2bfloat16(v - __bfloat162float(h));
}

// ---------------- aggregation: out = h + inv_deg * sum_{src} h[src] ----------------
// Warp per node; 8-deep gather unroll for MLP (indices hoisted before the batch).
__global__ void agg_kernel(const float4* __restrict__ h4, float4* __restrict__ out4) {
    int warp = (blockIdx.x * blockDim.x + threadIdx.x) >> 5;
    if (warp >= N_NODES) return;
    int lane = threadIdx.x & 31;

    int s = g_rowstart[warp];
    int e = g_rowstart[warp + 1];

    float4 acc = make_float4(0.f, 0.f, 0.f, 0.f);
    int i = s;
    for (; i + 8 <= e; i += 8) {
        int idx[8];
        #pragma unroll
        for (int j = 0; j < 8; j++) idx[j] = __ldg(&g_csr_src[i + j]);
        float4 v[8];
        #pragma unroll
        for (int j = 0; j < 8; j++) v[j] = __ldg(&h4[(size_t)idx[j] * 32 + lane]);
        float4 p0, p1, p2, p3;
        p0.x = v[0].x + v[1].x; p0.y = v[0].y + v[1].y; p0.z = v[0].z + v[1].z; p0.w = v[0].w + v[1].w;
        p1.x = v[2].x + v[3].x; p1.y = v[2].y + v[3].y; p1.z = v[2].z + v[3].z; p1.w = v[2].w + v[3].w;
        p2.x = v[4].x + v[5].x; p2.y = v[4].y + v[5].y; p2.z = v[4].z + v[5].z; p2.w = v[4].w + v[5].w;
        p3.x = v[6].x + v[7].x; p3.y = v[6].y + v[7].y; p3.z = v[6].z + v[7].z; p3.w = v[6].w + v[7].w;
        acc.x += (p0.x + p1.x) + (p2.x + p3.x);
        acc.y += (p0.y + p1.y) + (p2.y + p3.y);
        acc.z += (p0.z + p1.z) + (p2.z + p3.z);
        acc.w += (p0.w + p1.w) + (p2.w + p3.w);
    }
    if (i + 4 <= e) {
        int i0 = __ldg(&g_csr_src[i + 0]);
        int i1 = __ldg(&g_csr_src[i + 1]);
        int i2 = __ldg(&g_csr_src[i + 2]);
        int i3 = __ldg(&g_csr_src[i + 3]);
        float4 v0 = __ldg(&h4[(size_t)i0 * 32 + lane]);
        float4 v1 = __ldg(&h4[(size_t)i1 * 32 + lane]);
        float4 v2 = __ldg(&h4[(size_t)i2 * 32 + lane]);
        float4 v3 = __ldg(&h4[(size_t)i3 * 32 + lane]);
        acc.x += (v0.x + v1.x) + (v2.x + v3.x);
        acc.y += (v0.y + v1.y) + (v2.y + v3.y);
        acc.z += (v0.z + v1.z) + (v2.z + v3.z);
        acc.w += (v0.w + v1.w) + (v2.w + v3.w);
        i += 4;
    }
    for (; i < e; i++) {
        int s0 = __ldg(&g_csr_src[i]);
        float4 v = __ldg(&h4[(size_t)s0 * 32 + lane]);
        acc.x += v.x; acc.y += v.y; acc.z += v.z; acc.w += v.w;
    }

    float w = g_invdeg[warp];
    float4 self = __ldg(&h4[(size_t)warp * 32 + lane]);
    float4 o;
    o.x = self.x + acc.x * w;
    o.y = self.y + acc.y * w;
    o.z = self.z + acc.z * w;
    o.w = self.w + acc.w * w;
    out4[(size_t)warp * 32 + lane] = o;
}

// ---------------- HMMA GEMM: out[M,128] = [relu](A[M,128] @ W + b) ----------------
// bf16 hi/lo split via mma.sync: D = aHi*wHi + aHi*wLo + aLo*wHi.
#define APITCH 136
#define GEMM_SMEM_BYTES (4 * 128 * APITCH * 2)

__global__ void __launch_bounds__(256, 1)
mma_gemm_kernel(const float* __restrict__ A,
                const __nv_bfloat16* __restrict__ whi,
                const __nv_bfloat16* __restrict__ wlo,
                const float* __restrict__ bias,
                float* __restrict__ out, int M, int do_relu) {
    extern __shared__ __nv_bfloat16 sm[];
    __nv_bfloat16* sAhi = sm;
    __nv_bfloat16* sAlo = sm + 128 * APITCH;
    __nv_bfloat16* sWhi = sm + 2 * 128 * APITCH;
    __nv_bfloat16* sWlo = sm + 3 * 128 * APITCH;

    const int tid  = threadIdx.x;
    const int lane = tid & 31;
    const int wid  = tid >> 5;
    const int row0 = blockIdx.x * 128;
    const int rows = min(128, M - row0);

    if (rows < 128) {
        uint32_t z = 0;
        uint32_t base = smem_u32(sAhi);
        for (int idx = tid; idx < 2 * 128 * APITCH / 2; idx += 256)
            asm volatile("st.shared.b32 [%0], %1;" :: "r"(base + idx * 4), "r"(z) : "memory");
        __syncthreads();
    }

    {
        const float4* A4 = reinterpret_cast<const float4*>(A);
        for (int idx = tid; idx < rows * 32; idx += 256) {
            int r = idx >> 5, c4 = idx & 31;
            float4 a = __ldg(&A4[(size_t)(row0 + r) * 32 + c4]);
            __nv_bfloat162 h0 = __floats2bfloat162_rn(a.x, a.y);
            __nv_bfloat162 h1 = __floats2bfloat162_rn(a.z, a.w);
            float2 f0 = __bfloat1622float2(h0);
            float2 f1 = __bfloat1622float2(h1);
            __nv_bfloat162 l0 = __floats2bfloat162_rn(a.x - f0.x, a.y - f0.y);
            __nv_bfloat162 l1 = __floats2bfloat162_rn(a.z - f1.x, a.w - f1.y);
            int eoff = r * APITCH + c4 * 4;
            *reinterpret_cast<__nv_bfloat162*>(sAhi + eoff)     = h0;
            *reinterpret_cast<__nv_bfloat162*>(sAhi + eoff + 2) = h1;
            *reinterpret_cast<__nv_bfloat162*>(sAlo + eoff)     = l0;
            *reinterpret_cast<__nv_bfloat162*>(sAlo + eoff + 2) = l1;
        }
    }

    {
        const uint4* wh4 = reinterpret_cast<const uint4*>(whi);
        const uint4* wl4 = reinterpret_cast<const uint4*>(wlo);
        for (int idx = tid; idx < 2048; idx += 256) {
            int r = idx >> 4, c16 = idx & 15;
            int eoff = r * APITCH + c16 * 8;
            *reinterpret_cast<uint4*>(sWhi + eoff) = __ldg(&wh4[idx]);
            *reinterpret_cast<uint4*>(sWlo + eoff) = __ldg(&wl4[idx]);
        }
    }
    __syncthreads();

    const int wm = wid & 3;
    const int wn = wid >> 2;

    float acc[2][8][4];
    #pragma unroll
    for (int i = 0; i < 2; i++)
        #pragma unroll
        for (int j = 0; j < 8; j++)
            #pragma unroll
            for (int c = 0; c < 4; c++) acc[i][j][c] = 0.f;

    const uint32_t aRowOff = (uint32_t)(((wm * 32 + (lane & 15)) * APITCH + (lane >> 4) * 8) * 2);
    const uint32_t bRowOff = (uint32_t)(((wn * 64 + (lane & 7)) * APITCH + ((lane >> 3) & 1) * 8) * 2);

    #pragma unroll
    for (int pass = 0; pass < 3; pass++) {
        const __nv_bfloat16* pA = (pass == 2) ? sAlo : sAhi;
        const __nv_bfloat16* pW = (pass == 1) ? sWlo : sWhi;
        uint32_t aAddr = smem_u32(pA) + aRowOff;
        uint32_t bAddr = smem_u32(pW) + bRowOff;

        #pragma unroll
        for (int kk = 0; kk < 8; kk++) {
            uint32_t a0[4], a1[4];
            ldmatrix_x4(a0, aAddr + kk * 32);
            ldmatrix_x4(a1, aAddr + 16 * APITCH * 2 + kk * 32);
            #pragma unroll
            for (int tn = 0; tn < 8; tn++) {
                uint32_t b[2];
                ldmatrix_x2(b, bAddr + tn * 8 * APITCH * 2 + kk * 32);
                mma16816(acc[0][tn], a0, b);
                mma16816(acc[1][tn], a1, b);
            }
        }
    }

    #pragma unroll
    for (int tm = 0; tm < 2; tm++) {
        int rbase = wm * 32 + tm * 16 + (lane >> 2);
        #pragma unroll
        for (int half = 0; half < 2; half++) {
            int r = rbase + half * 8;
            if (r < rows) {
                float* orow = out + (size_t)(row0 + r) * 128;
                #pragma unroll
                for (int tn = 0; tn < 8; tn++) {
                    int c = wn * 64 + tn * 8 + (lane & 3) * 2;
                    float2 o;
                    o.x = acc[tm][tn][half * 2 + 0] + __ldg(&bias[c + 0]);
                    o.y = acc[tm][tn][half * 2 + 1] + __ldg(&bias[c + 1]);
                    if (do_relu) { o.x = fmaxf(o.x, 0.f); o.y = fmaxf(o.y, 0.f); }
                    *reinterpret_cast<float2*>(orow + c) = o;
                }
            }
        }
    }
}

// ---------------- launch ----------------
extern "C" void kernel_launch(void* const* d_in, const int* in_sizes, int n_in,
                              void* d_out, int out_size) {
    const float* x        = (const float*)d_in[0];
    const float* W1       = (const float*)d_in[1];
    const float* b1       = (const float*)d_in[2];
    const float* W2       = (const float*)d_in[3];
    const float* b2       = (const float*)d_in[4];
    const float* W3       = (const float*)d_in[5];
    const float* b3       = (const float*)d_in[6];
    const int*   edge_src = (const int*)d_in[7];
    const int*   edge_dst = (const int*)d_in[8];
    float* out = (float*)d_out;

    (void)in_sizes; (void)n_in; (void)out_size;

    cudaFuncSetAttribute(mma_gemm_kernel,
                         cudaFuncAttributeMaxDynamicSharedMemorySize, GEMM_SMEM_BYTES);

    float* bufA; float* bufB;
    __nv_bfloat16* whi; __nv_bfloat16* wlo;
    cudaGetSymbolAddress((void**)&bufA, g_bufA);
    cudaGetSymbolAddress((void**)&bufB, g_bufB);
    cudaGetSymbolAddress((void**)&whi, g_whi);
    cudaGetSymbolAddress((void**)&wlo, g_wlo);

    const int M = N_NODES;
    const int edgeBlocks = (N_EDGES + 255) / 256;
    const int nodeBlocks = (N_NODES + 255) / 256;
    const int aggBlocks  = (N_NODES * 32 + 255) / 256;
    const int gemmBlocks = (M + 127) / 128;

    // weight prep (independent; overlaps CSR build)
    convw_kernel<<<(3 * FEAT * FEAT + 255) / 256, 256>>>(W1, W2, W3);

    // CSR build (parallel 3-pass scan)
    zero_cursor_kernel<<<nodeBlocks, 256>>>();
    hist_kernel<<<edgeBlocks, 256>>>(edge_dst);
    scan_reduce_kernel<<<SCAN_NBLK, 256>>>();
    scan_blocksums_kernel<<<1, 256>>>();
    scan_write_kernel<<<SCAN_NBLK, SCAN_BLK>>>();
    scatter_kernel<<<edgeBlocks, 256>>>(edge_src, edge_dst);

    // layer 1
    agg_kernel<<<aggBlocks, 256>>>((const float4*)x, (float4*)bufA);
    mma_gemm_kernel<<<gemmBlocks, 256, GEMM_SMEM_BYTES>>>(bufA, whi, wlo, b1, bufB, M, 1);
    // layer 2
    agg_kernel<<<aggBlocks, 256>>>((const float4*)bufB, (float4*)bufA);
    mma_gemm_kernel<<<gemmBlocks, 256, GEMM_SMEM_BYTES>>>(bufA, whi + FEAT * FEAT, wlo + FEAT * FEAT, b2, bufB, M, 1);
    // layer 3
    agg_kernel<<<aggBlocks, 256>>>((const float4*)bufB, (float4*)bufA);
    mma_gemm_kernel<<<gemmBlocks, 256, GEMM_SMEM_BYTES>>>(bufA, whi + 2 * FEAT * FEAT, wlo + 2 * FEAT * FEAT, b3, out, M, 0);
}

// round 8
// speedup vs baseline: 1.1711x; 1.1111x over previous
#include <cuda_runtime.h>
#include <cuda_bf16.h>
#include <cstdint>

#define N_NODES 100000
#define N_EDGES 1600000
#define FEAT    128

#define SCAN_BLK   512
#define SCAN_NBLK  ((N_NODES + SCAN_BLK - 1) / SCAN_BLK)   // 196
#define NT_TILES   ((N_NODES + 127) / 128)                  // 782

// ---------------- device scratch (no allocations allowed) ----------------
__device__ float g_bufB[N_NODES * FEAT];                   // fp32 GEMM output (next layer input)
__device__ __nv_bfloat16 g_ahi[N_NODES * FEAT];            // agg output, bf16 hi
__device__ __nv_bfloat16 g_alo[N_NODES * FEAT];            // agg output, bf16 lo
__device__ int   g_rowstart[N_NODES + 1];
__device__ int   g_cursor[N_NODES];
__device__ float g_invdeg[N_NODES];
__device__ int   g_csr_src[N_EDGES];
__device__ int   g_blkoff[SCAN_NBLK];
__device__ __nv_bfloat16 g_whi[3 * FEAT * FEAT];           // [n][k] (K contiguous) = col-major B
__device__ __nv_bfloat16 g_wlo[3 * FEAT * FEAT];

// ---------------- helpers ----------------
__device__ __forceinline__ uint32_t smem_u32(const void* p) {
    uint32_t a;
    asm("{ .reg .u64 t; cvta.to.shared.u64 t, %1; cvt.u32.u64 %0, t; }" : "=r"(a) : "l"(p));
    return a;
}
__device__ __forceinline__ void cp_async16(uint32_t dst, const void* src) {
    asm volatile("cp.async.cg.shared.global [%0], [%1], 16;" :: "r"(dst), "l"(src) : "memory");
}
__device__ __forceinline__ void cp_commit() {
    asm volatile("cp.async.commit_group;" ::: "memory");
}
__device__ __forceinline__ void cp_wait0() {
    asm volatile("cp.async.wait_group 0;" ::: "memory");
}
__device__ __forceinline__ void ldmatrix_x4(uint32_t* r, uint32_t addr) {
    asm volatile("ldmatrix.sync.aligned.m8n8.x4.shared.b16 {%0,%1,%2,%3}, [%4];"
                 : "=r"(r[0]), "=r"(r[1]), "=r"(r[2]), "=r"(r[3]) : "r"(addr));
}
__device__ __forceinline__ void ldmatrix_x2(uint32_t* r, uint32_t addr) {
    asm volatile("ldmatrix.sync.aligned.m8n8.x2.shared.b16 {%0,%1}, [%2];"
                 : "=r"(r[0]), "=r"(r[1]) : "r"(addr));
}
__device__ __forceinline__ void mma16816(float* c, const uint32_t* a, const uint32_t* b) {
    asm volatile("mma.sync.aligned.m16n8k16.row.col.f32.bf16.bf16.f32 "
                 "{%0,%1,%2,%3}, {%4,%5,%6,%7}, {%8,%9}, {%0,%1,%2,%3};"
                 : "+f"(c[0]), "+f"(c[1]), "+f"(c[2]), "+f"(c[3])
                 : "r"(a[0]), "r"(a[1]), "r"(a[2]), "r"(a[3]), "r"(b[0]), "r"(b[1]));
}

// ---------------- prep: zero degree counters + convert weights ----------------
__global__ void prep_kernel(const float* __restrict__ W1, const float* __restrict__ W2,
                            const float* __restrict__ W3) {
    int i = blockIdx.x * blockDim.x + threadIdx.x;
    if (i < N_NODES) g_cursor[i] = 0;
    if (i < 3 * FEAT * FEAT) {
        int l = i >> 14, r = i & 16383;
        int n = r >> 7, k = r & 127;
        const float* W = (l == 0) ? W1 : ((l == 1) ? W2 : W3);
        float v = W[k * FEAT + n];
        __nv_bfloat16 h = __float2bfloat16(v);
        g_whi[i] = h;
        g_wlo[i] = __float2bfloat16(v - __bfloat162float(h));
    }
}

__global__ void hist_kernel(const int* __restrict__ dst) {
    int e = blockIdx.x * blockDim.x + threadIdx.x;
    if (e < N_EDGES) atomicAdd(&g_cursor[dst[e]], 1);
}

// single block: per-chunk sums (coalesced warp-per-chunk) + scan of 196 sums
__global__ void scan_combined_kernel() {
    __shared__ int csum[SCAN_NBLK];
    __shared__ int ws[8];
    int t = threadIdx.x;           // 1024
    int w = t >> 5, lane = t & 31;

    for (int c = w; c < SCAN_NBLK; c += 32) {
        int base = c * SCAN_BLK;
        int s = 0;
        for (int j = lane; j < SCAN_BLK; j += 32) {
            int idx = base + j;
            if (idx < N_NODES) s += g_cursor[idx];
        }
        #pragma unroll
        for (int off = 16; off > 0; off >>= 1) s += __shfl_down_sync(0xFFFFFFFFu, s, off);
        if (lane == 0) csum[c] = s;
    }
    __syncthreads();

    int v = (t < SCAN_NBLK) ? csum[t] : 0;
    int orig = v;
    #pragma unroll
    for (int off = 1; off < 32; off <<= 1) {
        int n = __shfl_up_sync(0xFFFFFFFFu, v, off);
        if (lane >= off) v += n;
    }
    if (lane == 31 && w < 8) ws[w] = v;
    __syncthreads();
    if (t < 8) {
        int s = ws[t];
        #pragma unroll
        for (int off = 1; off < 8; off <<= 1) {
            int n = __shfl_up_sync(0xFFu, s, off);
            if (t >= off) s += n;
        }
        ws[t] = s;
    }
    __syncthreads();
    int base2 = (w > 0 && w < 8) ? ws[w - 1] : 0;
    int incl = base2 + v;
    if (t < SCAN_NBLK) g_blkoff[t] = incl - orig;   // exclusive
    if (t == SCAN_NBLK - 1) g_rowstart[N_NODES] = incl;
}

// block-local exclusive scan + write rowstart/cursor/invdeg (coalesced)
__global__ void scan_write_kernel() {
    int i = blockIdx.x * SCAN_BLK + threadIdx.x;
    int d = (i < N_NODES) ? g_cursor[i] : 0;
    int lane = threadIdx.x & 31, w = threadIdx.x >> 5;
    int v = d;
    #pragma unroll
    for (int off = 1; off < 32; off <<= 1) {
        int n = __shfl_up_sync(0xFFFFFFFFu, v, off);
        if (lane >= off) v += n;
    }
    __shared__ int ws[16];
    if (lane == 31) ws[w] = v;
    __syncthreads();
    if (threadIdx.x < 16) {
        int s = ws[threadIdx.x];
        #pragma unroll
        for (int off = 1; off < 16; off <<= 1) {
            int n = __shfl_up_sync(0xFFFFu, s, off);
            if (threadIdx.x >= off) s += n;
        }
        ws[threadIdx.x] = s;
    }
    __syncthreads();
    int base = (w > 0) ? ws[w - 1] : 0;
    int excl = g_blkoff[blockIdx.x] + base + v - d;
    if (i < N_NODES) {
        g_rowstart[i] = excl;
        g_cursor[i]   = excl;
        g_invdeg[i]   = 1.0f / fmaxf((float)d, 1.0f);
    }
}

__global__ void scatter_kernel(const int* __restrict__ src, const int* __restrict__ dst) {
    int e = blockIdx.x * blockDim.x + threadIdx.x;
    if (e < N_EDGES) {
        int pos = atomicAdd(&g_cursor[dst[e]], 1);
        g_csr_src[pos] = src[e];
    }
}

// ---------------- aggregation: (h + mean_neighbors) split to bf16 hi/lo tables ----------------
__global__ void agg_kernel(const float4* __restrict__ hself) {
    int warp = (blockIdx.x * blockDim.x + threadIdx.x) >> 5;
    if (warp >= N_NODES) return;
    int lane = threadIdx.x & 31;

    int s = g_rowstart[warp];
    int e = g_rowstart[warp + 1];

    float4 acc = make_float4(0.f, 0.f, 0.f, 0.f);
    int i = s;
    for (; i + 4 <= e; i += 4) {
        int i0 = __ldg(&g_csr_src[i + 0]);
        int i1 = __ldg(&g_csr_src[i + 1]);
        int i2 = __ldg(&g_csr_src[i + 2]);
        int i3 = __ldg(&g_csr_src[i + 3]);
        float4 v0 = __ldg(&hself[(size_t)i0 * 32 + lane]);
        float4 v1 = __ldg(&hself[(size_t)i1 * 32 + lane]);
        float4 v2 = __ldg(&hself[(size_t)i2 * 32 + lane]);
        float4 v3 = __ldg(&hself[(size_t)i3 * 32 + lane]);
        acc.x += (v0.x + v1.x) + (v2.x + v3.x);
        acc.y += (v0.y + v1.y) + (v2.y + v3.y);
        acc.z += (v0.z + v1.z) + (v2.z + v3.z);
        acc.w += (v0.w + v1.w) + (v2.w + v3.w);
    }
    for (; i < e; i++) {
        int s0 = __ldg(&g_csr_src[i]);
        float4 v = __ldg(&hself[(size_t)s0 * 32 + lane]);
        acc.x += v.x; acc.y += v.y; acc.z += v.z; acc.w += v.w;
    }

    float w = g_invdeg[warp];
    float4 self = __ldg(&hself[(size_t)warp * 32 + lane]);
    float4 o;
    o.x = self.x + acc.x * w;
    o.y = self.y + acc.y * w;
    o.z = self.z + acc.z * w;
    o.w = self.w + acc.w * w;

    // split to bf16 hi/lo and write the GEMM's A tables
    __nv_bfloat162 h0 = __floats2bfloat162_rn(o.x, o.y);
    __nv_bfloat162 h1 = __floats2bfloat162_rn(o.z, o.w);
    float2 f0 = __bfloat1622float2(h0);
    float2 f1 = __bfloat1622float2(h1);
    __nv_bfloat162 l0 = __floats2bfloat162_rn(o.x - f0.x, o.y - f0.y);
    __nv_bfloat162 l1 = __floats2bfloat162_rn(o.z - f1.x, o.w - f1.y);
    uint2 hv, lv;
    hv.x = *reinterpret_cast<uint32_t*>(&h0);
    hv.y = *reinterpret_cast<uint32_t*>(&h1);
    lv.x = *reinterpret_cast<uint32_t*>(&l0);
    lv.y = *reinterpret_cast<uint32_t*>(&l1);
    reinterpret_cast<uint2*>(g_ahi)[(size_t)warp * 32 + lane] = hv;
    reinterpret_cast<uint2*>(g_alo)[(size_t)warp * 32 + lane] = lv;
}

// ---------------- persistent HMMA GEMM: out[M,128] = [relu](A @ W + b) ----------------
// A pre-split to bf16 hi/lo tables; cp.async double-buffered tiles; W resident per block.
// D = aHi*wHi + aHi*wLo + aLo*wHi (fp32 accum).
#define APITCH 136
#define TILE_E (128 * APITCH)                       // bf16 elems per tile buffer
#define GEMM_SMEM_BYTES (6 * TILE_E * 2 + 512)      // W hi/lo + 2x A(hi/lo) bufs + bias

__global__ void __launch_bounds__(256, 1)
mma_gemm_kernel(const __nv_bfloat16* __restrict__ Ahi,
                const __nv_bfloat16* __restrict__ Alo,
                const __nv_bfloat16* __restrict__ whi,
                const __nv_bfloat16* __restrict__ wlo,
                const float* __restrict__ bias,
                float* __restrict__ out, int M, int do_relu) {
    extern __shared__ __nv_bfloat16 sm[];
    __nv_bfloat16* sWhi = sm;
    __nv_bfloat16* sWlo = sm + TILE_E;
    __nv_bfloat16* sA   = sm + 2 * TILE_E;          // [buf][hi/lo][TILE_E]
    float* sBias = reinterpret_cast<float*>(sm + 6 * TILE_E);

    const int tid  = threadIdx.x;
    const int lane = tid & 31;
    const int wid  = tid >> 5;
    const int NT   = (M + 127) / 128;
    const int step = gridDim.x;

    // resident W + bias (once per block)
    {
        const uint4* wh4 = reinterpret_cast<const uint4*>(whi);
        const uint4* wl4 = reinterpret_cast<const uint4*>(wlo);
        for (int idx = tid; idx < 2048; idx += 256) {
            int r = idx >> 4, c16 = idx & 15;
            int eoff = r * APITCH + c16 * 8;
            *reinterpret_cast<uint4*>(sWhi + eoff) = __ldg(&wh4[idx]);
            *reinterpret_cast<uint4*>(sWlo + eoff) = __ldg(&wl4[idx]);
        }
        if (tid < 32)
            reinterpret_cast<float4*>(sBias)[tid] = __ldg(&reinterpret_cast<const float4*>(bias)[tid]);
    }

    const uint32_t sAaddr = smem_u32(sA);
    const uint32_t wmBase = smem_u32(sWhi);

    // issue one tile's cp.async (hi+lo) into buffer `buf`
    auto issue_tile = [&](int tile, int buf) {
        int row0 = tile * 128;
        int rows = min(128, M - row0);
        int nchunk = rows * 16;                      // 16B chunks per table
        const char* srcHi = reinterpret_cast<const char*>(Ahi + (size_t)row0 * 128);
        const char* srcLo = reinterpret_cast<const char*>(Alo + (size_t)row0 * 128);
        uint32_t dstHi = sAaddr + (uint32_t)(buf * 2) * (TILE_E * 2);
        uint32_t dstLo = dstHi + TILE_E * 2;
        for (int idx = tid; idx < nchunk; idx += 256) {
            int r = idx >> 4, c = idx & 15;
            uint32_t doff = (uint32_t)(r * (APITCH * 2) + c * 16);
            int soff = r * 256 + c * 16;
            cp_async16(dstHi + doff, srcHi + soff);
            cp_async16(dstLo + doff, srcLo + soff);
        }
        cp_commit();
    };

    const int wm = wid & 3;
    const int wn = wid >> 2;
    const uint32_t aRowOff = (uint32_t)(((wm * 32 + (lane & 15)) * APITCH + (lane >> 4) * 8) * 2);
    const uint32_t bRowOff = (uint32_t)(((wn * 64 + (lane & 7)) * APITCH + ((lane >> 3) & 1) * 8) * 2);

    int t0 = blockIdx.x;
    if (t0 < NT) issue_tile(t0, 0);

    int i = 0;
    for (int t = t0; t < NT; t += step, i++) {
        int buf = i & 1;
        cp_wait0();
        __syncthreads();
        int nt = t + step;
        if (nt < NT) issue_tile(nt, buf ^ 1);

        // ---- MMA on buf ----
        float acc[2][8][4];
        #pragma unroll
        for (int a = 0; a < 2; a++)
            #pragma unroll
            for (int b = 0; b < 8; b++)
                #pragma unroll
                for (int c = 0; c < 4; c++) acc[a][b][c] = 0.f;

        uint32_t aHiB = sAaddr + (uint32_t)(buf * 2) * (TILE_E * 2);
        uint32_t aLoB = aHiB + TILE_E * 2;

        #pragma unroll
        for (int pass = 0; pass < 3; pass++) {
            uint32_t aAddr = ((pass == 2) ? aLoB : aHiB) + aRowOff;
            uint32_t bAddr = wmBase + ((pass == 1) ? (uint32_t)(TILE_E * 2) : 0u) + bRowOff;

            #pragma unroll
            for (int kk = 0; kk < 8; kk++) {
                uint32_t a0[4], a1[4];
                ldmatrix_x4(a0, aAddr + kk * 32);
                ldmatrix_x4(a1, aAddr + 16 * APITCH * 2 + kk * 32);
                #pragma unroll
                for (int tn = 0; tn < 8; tn++) {
                    uint32_t b[2];
                    ldmatrix_x2(b, bAddr + tn * 8 * APITCH * 2 + kk * 32);
                    mma16816(acc[0][tn], a0, b);
                    mma16816(acc[1][tn], a1, b);
                }
            }
        }

        // ---- epilogue ----
        int row0 = t * 128;
        int rows = min(128, M - row0);
        #pragma unroll
        for (int tm = 0; tm < 2; tm++) {
            int rbase = wm * 32 + tm * 16 + (lane >> 2);
            #pragma unroll
            for (int half = 0; half < 2; half++) {
                int r = rbase + half * 8;
                if (r < rows) {
                    float* orow = out + (size_t)(row0 + r) * 128;
                    #pragma unroll
                    for (int tn = 0; tn < 8; tn++) {
                        int c = wn * 64 + tn * 8 + (lane & 3) * 2;
                        float2 o;
                        o.x = acc[tm][tn][half * 2 + 0] + sBias[c + 0];
                        o.y = acc[tm][tn][half * 2 + 1] + sBias[c + 1];
                        if (do_relu) { o.x = fmaxf(o.x, 0.f); o.y = fmaxf(o.y, 0.f); }
                        *reinterpret_cast<float2*>(orow + c) = o;
                    }
                }
            }
        }
    }
}

// ---------------- launch ----------------
extern "C" void kernel_launch(void* const* d_in, const int* in_sizes, int n_in,
                              void* d_out, int out_size) {
    const float* x        = (const float*)d_in[0];
    const float* W1       = (const float*)d_in[1];
    const float* b1       = (const float*)d_in[2];
    const float* W2       = (const float*)d_in[3];
    const float* b2       = (const float*)d_in[4];
    const float* W3       = (const float*)d_in[5];
    const float* b3       = (const float*)d_in[6];
    const int*   edge_src = (const int*)d_in[7];
    const int*   edge_dst = (const int*)d_in[8];
    float* out = (float*)d_out;

    (void)in_sizes; (void)n_in; (void)out_size;

    cudaFuncSetAttribute(mma_gemm_kernel,
                         cudaFuncAttributeMaxDynamicSharedMemorySize, GEMM_SMEM_BYTES);

    int numSM = 148;
    cudaDeviceGetAttribute(&numSM, cudaDevAttrMultiProcessorCount, 0);

    float* bufB;
    __nv_bfloat16 *whi, *wlo, *ahi, *alo;
    cudaGetSymbolAddress((void**)&bufB, g_bufB);
    cudaGetSymbolAddress((void**)&whi, g_whi);
    cudaGetSymbolAddress((void**)&wlo, g_wlo);
    cudaGetSymbolAddress((void**)&ahi, g_ahi);
    cudaGetSymbolAddress((void**)&alo, g_alo);

    const int M = N_NODES;
    const int edgeBlocks = (N_EDGES + 255) / 256;
    const int prepBlocks = (N_NODES + 255) / 256;
    const int aggBlocks  = (N_NODES * 32 + 255) / 256;

    // CSR build + weight prep
    prep_kernel<<<prepBlocks, 256>>>(W1, W2, W3);                 // 1
    hist_kernel<<<edgeBlocks, 256>>>(edge_dst);                   // 2
    scan_combined_kernel<<<1, 1024>>>();                          // 3
    scan_write_kernel<<<SCAN_NBLK, SCAN_BLK>>>();                 // 4
    scatter_kernel<<<edgeBlocks, 256>>>(edge_src, edge_dst);      // 5

    // layer 1                                                    // 6 = agg (ncu capture slot)
    agg_kernel<<<aggBlocks, 256>>>((const float4*)x);
    mma_gemm_kernel<<<numSM, 256, GEMM_SMEM_BYTES>>>(ahi, alo, whi, wlo, b1, bufB, M, 1);
    // layer 2
    agg_kernel<<<aggBlocks, 256>>>((const float4*)bufB);
    mma_gemm_kernel<<<numSM, 256, GEMM_SMEM_BYTES>>>(ahi, alo, whi + FEAT * FEAT, wlo + FEAT * FEAT, b2, bufB, M, 1);
    // layer 3
    agg_kernel<<<aggBlocks, 256>>>((const float4*)bufB);
    mma_gemm_kernel<<<numSM, 256, GEMM_SMEM_BYTES>>>(ahi, alo, whi + 2 * FEAT * FEAT, wlo + 2 * FEAT * FEAT, b3, out, M, 0);
}

// round 9
// speedup vs baseline: 1.1969x; 1.0220x over previous
#include <cuda_runtime.h>
#include <cuda_bf16.h>
#include <cstdint>

#define N_NODES 100000
#define N_EDGES 1600000
#define FEAT    128

#define SCAN_BLK   512
#define SCAN_NBLK  ((N_NODES + SCAN_BLK - 1) / SCAN_BLK)   // 196

// ---------------- device scratch (no allocations allowed) ----------------
__device__ float g_bufB[N_NODES * FEAT];                   // fp32 GEMM output (next layer input)
__device__ __nv_bfloat16 g_ahi[N_NODES * FEAT];            // agg output, bf16 hi
__device__ __nv_bfloat16 g_alo[N_NODES * FEAT];            // agg output, bf16 lo
__device__ int   g_histcnt[N_NODES];                       // degree histogram (zeroed at END of call)
__device__ int   g_rowstart[N_NODES + 1];
__device__ int   g_cursor[N_NODES];
__device__ float g_invdeg[N_NODES];
__device__ int   g_csr_src[N_EDGES];
__device__ int   g_aggval[SCAN_NBLK];
__device__ int   g_count;                                  // grid-sync counter (zeroed at END)
__device__ __nv_bfloat16 g_whi[3 * FEAT * FEAT];           // [n][k] (K contiguous) = col-major B
__device__ __nv_bfloat16 g_wlo[3 * FEAT * FEAT];

// ---------------- helpers ----------------
__device__ __forceinline__ uint32_t smem_u32(const void* p) {
    uint32_t a;
    asm("{ .reg .u64 t; cvta.to.shared.u64 t, %1; cvt.u32.u64 %0, t; }" : "=r"(a) : "l"(p));
    return a;
}
__device__ __forceinline__ void cp_async16(uint32_t dst, const void* src) {
    asm volatile("cp.async.cg.shared.global [%0], [%1], 16;" :: "r"(dst), "l"(src) : "memory");
}
__device__ __forceinline__ void cp_commit() {
    asm volatile("cp.async.commit_group;" ::: "memory");
}
__device__ __forceinline__ void cp_wait0() {
    asm volatile("cp.async.wait_group 0;" ::: "memory");
}
__device__ __forceinline__ void ldmatrix_x4(uint32_t* r, uint32_t addr) {
    asm volatile("ldmatrix.sync.aligned.m8n8.x4.shared.b16 {%0,%1,%2,%3}, [%4];"
                 : "=r"(r[0]), "=r"(r[1]), "=r"(r[2]), "=r"(r[3]) : "r"(addr));
}
__device__ __forceinline__ void ldmatrix_x2(uint32_t* r, uint32_t addr) {
    asm volatile("ldmatrix.sync.aligned.m8n8.x2.shared.b16 {%0,%1}, [%2];"
                 : "=r"(r[0]), "=r"(r[1]) : "r"(addr));
}
__device__ __forceinline__ void mma16816(float* c, const uint32_t* a, const uint32_t* b) {
    asm volatile("mma.sync.aligned.m16n8k16.row.col.f32.bf16.bf16.f32 "
                 "{%0,%1,%2,%3}, {%4,%5,%6,%7}, {%8,%9}, {%0,%1,%2,%3};"
                 : "+f"(c[0]), "+f"(c[1]), "+f"(c[2]), "+f"(c[3])
                 : "r"(a[0]), "r"(a[1]), "r"(a[2]), "r"(a[3]), "r"(b[0]), "r"(b[1]));
}

// ---------------- CSR build ----------------
// hist: 4 edges per thread (int4); g_histcnt is zero on entry (invariant).
__global__ void hist_kernel(const int4* __restrict__ dst4) {
    int t = blockIdx.x * blockDim.x + threadIdx.x;
    if (t < N_EDGES / 4) {
        int4 d = __ldg(&dst4[t]);
        atomicAdd(&g_histcnt[d.x], 1);
        atomicAdd(&g_histcnt[d.y], 1);
        atomicAdd(&g_histcnt[d.z], 1);
        atomicAdd(&g_histcnt[d.w], 1);
    }
}

// single-kernel device-wide exclusive scan over degrees (196 co-resident blocks,
// grid sync via atomic counter; all blocks resident -> spin is safe).
__global__ void scan_fused_kernel() {
    int b = blockIdx.x, tid = threadIdx.x;
    int i = b * SCAN_BLK + tid;
    int d = (i < N_NODES) ? g_histcnt[i] : 0;
    int lane = tid & 31, w = tid >> 5;

    // block inclusive scan
    int v = d;
    #pragma unroll
    for (int off = 1; off < 32; off <<= 1) {
        int n = __shfl_up_sync(0xFFFFFFFFu, v, off);
        if (lane >= off) v += n;
    }
    __shared__ int ws[16];
    if (lane == 31) ws[w] = v;
    __syncthreads();
    if (tid < 16) {
        int s = ws[tid];
        #pragma unroll
        for (int off = 1; off < 16; off <<= 1) {
            int n = __shfl_up_sync(0xFFFFu, s, off);
            if (tid >= off) s += n;
        }
        ws[tid] = s;
    }
    __syncthreads();
    int incl = ((w > 0) ? ws[w - 1] : 0) + v;
    int T = ws[15];   // block total

    // publish total, grid-sync
    if (tid == 0) {
        g_aggval[b] = T;
        __threadfence();
        atomicAdd(&g_count, 1);
        while (atomicAdd(&g_count, 0) < SCAN_NBLK) { }
    }
    __syncthreads();

    // base = sum of predecessors' totals (volatile loads; block reduce)
    int contrib = 0;
    if (tid < b) contrib = *((volatile int*)&g_aggval[tid]);
    #pragma unroll
    for (int off = 16; off > 0; off >>= 1) contrib += __shfl_down_sync(0xFFFFFFFFu, contrib, off);
    __shared__ int rs[16];
    if (lane == 0) rs[w] = contrib;
    __syncthreads();
    __shared__ int baseS;
    if (tid < 16) {
        int s = rs[tid];
        #pragma unroll
        for (int off = 8; off > 0; off >>= 1) s += __shfl_down_sync(0xFFFFu, s, off);
        if (tid == 0) baseS = s;
    }
    __syncthreads();
    int base = baseS;

    int excl = base + incl - d;
    if (i < N_NODES) {
        g_rowstart[i] = excl;
        g_cursor[i]   = excl;
        g_invdeg[i]   = 1.0f / fmaxf((float)d, 1.0f);
    }
    if (b == SCAN_NBLK - 1 && tid == SCAN_BLK - 1) g_rowstart[N_NODES] = base + incl;
}

// scatter: 4 edges per thread
__global__ void scatter_kernel(const int4* __restrict__ src4, const int4* __restrict__ dst4) {
    int t = blockIdx.x * blockDim.x + threadIdx.x;
    if (t < N_EDGES / 4) {
        int4 s = __ldg(&src4[t]);
        int4 d = __ldg(&dst4[t]);
        g_csr_src[atomicAdd(&g_cursor[d.x], 1)] = s.x;
        g_csr_src[atomicAdd(&g_cursor[d.y], 1)] = s.y;
        g_csr_src[atomicAdd(&g_cursor[d.z], 1)] = s.z;
        g_csr_src[atomicAdd(&g_cursor[d.w], 1)] = s.w;
    }
}

// restore the zero-invariant for the next call
__global__ void cleanup_kernel() {
    int i = blockIdx.x * blockDim.x + threadIdx.x;
    if (i < N_NODES) g_histcnt[i] = 0;
    if (i == 0) g_count = 0;
}

// ---------------- weight prep: fp32 W[k][n] -> bf16 hi/lo in [n][k] ----------------
__global__ void convw_kernel(const float* __restrict__ W1, const float* __restrict__ W2,
                             const float* __restrict__ W3) {
    int i = blockIdx.x * blockDim.x + threadIdx.x;
    if (i >= 3 * FEAT * FEAT) return;
    int l = i >> 14, r = i & 16383;
    int n = r >> 7, k = r & 127;
    const float* W = (l == 0) ? W1 : ((l == 1) ? W2 : W3);
    float v = W[k * FEAT + n];
    __nv_bfloat16 h = __float2bfloat16(v);
    g_whi[i] = h;
    g_wlo[i] = __float2bfloat16(v - __bfloat162float(h));
}

// ---------------- aggregation: (h + mean_neighbors) split to bf16 hi/lo tables ----------------
__global__ void agg_kernel(const float4* __restrict__ hself) {
    int warp = (blockIdx.x * blockDim.x + threadIdx.x) >> 5;
    if (warp >= N_NODES) return;
    int lane = threadIdx.x & 31;

    int s = g_rowstart[warp];
    int e = g_rowstart[warp + 1];

    float4 acc = make_float4(0.f, 0.f, 0.f, 0.f);
    int i = s;
    for (; i + 4 <= e; i += 4) {
        int i0 = __ldg(&g_csr_src[i + 0]);
        int i1 = __ldg(&g_csr_src[i + 1]);
        int i2 = __ldg(&g_csr_src[i + 2]);
        int i3 = __ldg(&g_csr_src[i + 3]);
        float4 v0 = __ldg(&hself[(size_t)i0 * 32 + lane]);
        float4 v1 = __ldg(&hself[(size_t)i1 * 32 + lane]);
        float4 v2 = __ldg(&hself[(size_t)i2 * 32 + lane]);
        float4 v3 = __ldg(&hself[(size_t)i3 * 32 + lane]);
        acc.x += (v0.x + v1.x) + (v2.x + v3.x);
        acc.y += (v0.y + v1.y) + (v2.y + v3.y);
        acc.z += (v0.z + v1.z) + (v2.z + v3.z);
        acc.w += (v0.w + v1.w) + (v2.w + v3.w);
    }
    for (; i < e; i++) {
        int s0 = __ldg(&g_csr_src[i]);
        float4 v = __ldg(&hself[(size_t)s0 * 32 + lane]);
        acc.x += v.x; acc.y += v.y; acc.z += v.z; acc.w += v.w;
    }

    float w = g_invdeg[warp];
    float4 self = __ldg(&hself[(size_t)warp * 32 + lane]);
    float4 o;
    o.x = self.x + acc.x * w;
    o.y = self.y + acc.y * w;
    o.z = self.z + acc.z * w;
    o.w = self.w + acc.w * w;

    __nv_bfloat162 h0 = __floats2bfloat162_rn(o.x, o.y);
    __nv_bfloat162 h1 = __floats2bfloat162_rn(o.z, o.w);
    float2 f0 = __bfloat1622float2(h0);
    float2 f1 = __bfloat1622float2(h1);
    __nv_bfloat162 l0 = __floats2bfloat162_rn(o.x - f0.x, o.y - f0.y);
    __nv_bfloat162 l1 = __floats2bfloat162_rn(o.z - f1.x, o.w - f1.y);
    uint2 hv, lv;
    hv.x = *reinterpret_cast<uint32_t*>(&h0);
    hv.y = *reinterpret_cast<uint32_t*>(&h1);
    lv.x = *reinterpret_cast<uint32_t*>(&l0);
    lv.y = *reinterpret_cast<uint32_t*>(&l1);
    reinterpret_cast<uint2*>(g_ahi)[(size_t)warp * 32 + lane] = hv;
    reinterpret_cast<uint2*>(g_alo)[(size_t)warp * 32 + lane] = lv;
}

// ---------------- persistent HMMA GEMM: out[M,128] = [relu](A @ W + b) ----------------
#define APITCH 136
#define TILE_E (128 * APITCH)
#define GEMM_SMEM_BYTES (6 * TILE_E * 2 + 512)

__global__ void __launch_bounds__(256, 1)
mma_gemm_kernel(const __nv_bfloat16* __restrict__ Ahi,
                const __nv_bfloat16* __restrict__ Alo,
                const __nv_bfloat16* __restrict__ whi,
                const __nv_bfloat16* __restrict__ wlo,
                const float* __restrict__ bias,
                float* __restrict__ out, int M, int do_relu) {
    extern __shared__ __nv_bfloat16 sm[];
    __nv_bfloat16* sWhi = sm;
    __nv_bfloat16* sWlo = sm + TILE_E;
    __nv_bfloat16* sA   = sm + 2 * TILE_E;
    float* sBias = reinterpret_cast<float*>(sm + 6 * TILE_E);

    const int tid  = threadIdx.x;
    const int lane = tid & 31;
    const int wid  = tid >> 5;
    const int NT   = (M + 127) / 128;
    const int step = gridDim.x;

    {
        const uint4* wh4 = reinterpret_cast<const uint4*>(whi);
        const uint4* wl4 = reinterpret_cast<const uint4*>(wlo);
        for (int idx = tid; idx < 2048; idx += 256) {
            int r = idx >> 4, c16 = idx & 15;
            int eoff = r * APITCH + c16 * 8;
            *reinterpret_cast<uint4*>(sWhi + eoff) = __ldg(&wh4[idx]);
            *reinterpret_cast<uint4*>(sWlo + eoff) = __ldg(&wl4[idx]);
        }
        if (tid < 32)
            reinterpret_cast<float4*>(sBias)[tid] = __ldg(&reinterpret_cast<const float4*>(bias)[tid]);
    }

    const uint32_t sAaddr = smem_u32(sA);
    const uint32_t wmBase = smem_u32(sWhi);

    auto issue_tile = [&](int tile, int buf) {
        int row0 = tile * 128;
        int rows = min(128, M - row0);
        int nchunk = rows * 16;
        const char* srcHi = reinterpret_cast<const char*>(Ahi + (size_t)row0 * 128);
        const char* srcLo = reinterpret_cast<const char*>(Alo + (size_t)row0 * 128);
        uint32_t dstHi = sAaddr + (uint32_t)(buf * 2) * (TILE_E * 2);
        uint32_t dstLo = dstHi + TILE_E * 2;
        for (int idx = tid; idx < nchunk; idx += 256) {
            int r = idx >> 4, c = idx & 15;
            uint32_t doff = (uint32_t)(r * (APITCH * 2) + c * 16);
            int soff = r * 256 + c * 16;
            cp_async16(dstHi + doff, srcHi + soff);
            cp_async16(dstLo + doff, srcLo + soff);
        }
        cp_commit();
    };

    const int wm = wid & 3;
    const int wn = wid >> 2;
    const uint32_t aRowOff = (uint32_t)(((wm * 32 + (lane & 15)) * APITCH + (lane >> 4) * 8) * 2);
    const uint32_t bRowOff = (uint32_t)(((wn * 64 + (lane & 7)) * APITCH + ((lane >> 3) & 1) * 8) * 2);

    int t0 = blockIdx.x;
    if (t0 < NT) issue_tile(t0, 0);

    int i = 0;
    for (int t = t0; t < NT; t += step, i++) {
        int buf = i & 1;
        cp_wait0();
        __syncthreads();
        int nt = t + step;
        if (nt < NT) issue_tile(nt, buf ^ 1);

        float acc[2][8][4];
        #pragma unroll
        for (int a = 0; a < 2; a++)
            #pragma unroll
            for (int b = 0; b < 8; b++)
                #pragma unroll
                for (int c = 0; c < 4; c++) acc[a][b][c] = 0.f;

        uint32_t aHiB = sAaddr + (uint32_t)(buf * 2) * (TILE_E * 2);
        uint32_t aLoB = aHiB + TILE_E * 2;

        #pragma unroll
        for (int pass = 0; pass < 3; pass++) {
            uint32_t aAddr = ((pass == 2) ? aLoB : aHiB) + aRowOff;
            uint32_t bAddr = wmBase + ((pass == 1) ? (uint32_t)(TILE_E * 2) : 0u) + bRowOff;

            #pragma unroll
            for (int kk = 0; kk < 8; kk++) {
                uint32_t a0[4], a1[4];
                ldmatrix_x4(a0, aAddr + kk * 32);
                ldmatrix_x4(a1, aAddr + 16 * APITCH * 2 + kk * 32);
                #pragma unroll
                for (int tn = 0; tn < 8; tn++) {
                    uint32_t b[2];
                    ldmatrix_x2(b, bAddr + tn * 8 * APITCH * 2 + kk * 32);
                    mma16816(acc[0][tn], a0, b);
                    mma16816(acc[1][tn], a1, b);
                }
            }
        }

        int row0 = t * 128;
        int rows = min(128, M - row0);
        #pragma unroll
        for (int tm = 0; tm < 2; tm++) {
            int rbase = wm * 32 + tm * 16 + (lane >> 2);
            #pragma unroll
            for (int half = 0; half < 2; half++) {
                int r = rbase + half * 8;
                if (r < rows) {
                    float* orow = out + (size_t)(row0 + r) * 128;
                    #pragma unroll
                    for (int tn = 0; tn < 8; tn++) {
                        int c = wn * 64 + tn * 8 + (lane & 3) * 2;
                        float2 o;
                        o.x = acc[tm][tn][half * 2 + 0] + sBias[c + 0];
                        o.y = acc[tm][tn][half * 2 + 1] + sBias[c + 1];
                        if (do_relu) { o.x = fmaxf(o.x, 0.f); o.y = fmaxf(o.y, 0.f); }
                        *reinterpret_cast<float2*>(orow + c) = o;
                    }
                }
            }
        }
    }
}

// ---------------- launch ----------------
extern "C" void kernel_launch(void* const* d_in, const int* in_sizes, int n_in,
                              void* d_out, int out_size) {
    const float* x        = (const float*)d_in[0];
    const float* W1       = (const float*)d_in[1];
    const float* b1       = (const float*)d_in[2];
    const float* W2       = (const float*)d_in[3];
    const float* b2       = (const float*)d_in[4];
    const float* W3       = (const float*)d_in[5];
    const float* b3       = (const float*)d_in[6];
    const int*   edge_src = (const int*)d_in[7];
    const int*   edge_dst = (const int*)d_in[8];
    float* out = (float*)d_out;

    (void)in_sizes; (void)n_in; (void)out_size;

    cudaFuncSetAttribute(mma_gemm_kernel,
                         cudaFuncAttributeMaxDynamicSharedMemorySize, GEMM_SMEM_BYTES);

    int numSM = 148;
    cudaDeviceGetAttribute(&numSM, cudaDevAttrMultiProcessorCount, 0);

    float* bufB;
    __nv_bfloat16 *whi, *wlo, *ahi, *alo;
    cudaGetSymbolAddress((void**)&bufB, g_bufB);
    cudaGetSymbolAddress((void**)&whi, g_whi);
    cudaGetSymbolAddress((void**)&wlo, g_wlo);
    cudaGetSymbolAddress((void**)&ahi, g_ahi);
    cudaGetSymbolAddress((void**)&alo, g_alo);

    const int M = N_NODES;
    const int edge4Blocks = (N_EDGES / 4 + 255) / 256;
    const int aggBlocks   = (N_NODES * 32 + 255) / 256;
    const int nodeBlocks  = (N_NODES + 255) / 256;

    // CSR build — g_histcnt/g_count are zero on entry (zero-init first call, cleanup after)
    hist_kernel<<<edge4Blocks, 256>>>((const int4*)edge_dst);            // launch 0
    scan_fused_kernel<<<SCAN_NBLK, SCAN_BLK>>>();                        // launch 1
    scatter_kernel<<<edge4Blocks, 256>>>((const int4*)edge_src,
                                         (const int4*)edge_dst);         // launch 2
    // layer 1
    agg_kernel<<<aggBlocks, 256>>>((const float4*)x);                    // launch 3 (profiled)
    convw_kernel<<<(3 * FEAT * FEAT + 255) / 256, 256>>>(W1, W2, W3);    // launch 4
    mma_gemm_kernel<<<numSM, 256, GEMM_SMEM_BYTES>>>(ahi, alo, whi, wlo, b1, bufB, M, 1);
    // layer 2
    agg_kernel<<<aggBlocks, 256>>>((const float4*)bufB);
    mma_gemm_kernel<<<numSM, 256, GEMM_SMEM_BYTES>>>(ahi, alo, whi + FEAT * FEAT, wlo + FEAT * FEAT, b2, bufB, M, 1);
    // layer 3
    agg_kernel<<<aggBlocks, 256>>>((const float4*)bufB);
    mma_gemm_kernel<<<numSM, 256, GEMM_SMEM_BYTES>>>(ahi, alo, whi + 2 * FEAT * FEAT, wlo + 2 * FEAT * FEAT, b3, out, M, 0);
    // restore zero-invariant for next call
    cleanup_kernel<<<nodeBlocks, 256>>>();
}